// round 1
// baseline (speedup 1.0000x reference)
#include <cuda_runtime.h>
#include <math.h>

#define Bsz  8192
#define DIN  1024
#define Hdim 2048
#define DOUTn 1024
#define Pn   4
#define En   6
#define Cn   512
#define CHn  256

// ---- scratch layout inside one big device array ----
#define OFF_H      0L
#define OFF_W      16777216L
#define OFF_D      41943040L
#define OFF_GLUED  67108864L
#define OFF_BASE   83886080L
#define OFF_TOTAL  88080384L
#define OFF_A1     92274688L
#define OFF_A2     92536832L
#define OFF_WBM    92798976L
#define OFF_WFM    92930048L
#define OFF_BBM    93061120L
#define OFF_BFM    93061376L
#define OFF_BTOT   93061632L
#define OFF_COBSQ  93062144L
#define OFF_PART   93111296L
#define SCRATCH_SZ 93112320L

__device__ float g_scratch[SCRATCH_SZ];

// ---- output layout in d_out (tuple order: output, diffused, h1_norm, h1_loss, total) ----
#define OUT_OUTPUT 0L
#define OUT_DIFF   8388608L
#define OUT_H1N    25165824L
#define OUT_H1L    25174016L
#define OUT_TOTAL  25174017L

// ============================================================================
// Generic fp32 SGEMM: 128x128 block tile, BK=8, 256 threads, 8x8 per thread.
// MODE 0: C = acc (+ bias[col])
// MODE 1: C += acc
// MODE 2: red_out[blockLinear] = sum(acc^2)              (scalar reduce)
// MODE 3: atomicAdd(red_out[row*red_stride + z], rowsumsq) (per-row reduce)
// Requires M%128==0, N%128==0, K%8==0 (true for all calls here).
// ============================================================================
template<int MODE>
__global__ __launch_bounds__(256, 2)
void sgemm(const float* __restrict__ A, const float* __restrict__ Bm,
           float* __restrict__ Cm,
           int K, int lda, int ldb, int ldc,
           long batchA, long batchB, long batchC,
           const float* __restrict__ bias,
           float* __restrict__ red_out, int red_stride)
{
    __shared__ float As[8][128];
    __shared__ float Bs[8][128];

    const int tid = threadIdx.x;
    const int ty = tid >> 4;      // 0..15
    const int tx = tid & 15;      // 0..15

    const float* Ab = A + (long)blockIdx.z * batchA + (long)(blockIdx.y * 128) * lda;
    const float* Bb = Bm + (long)blockIdx.z * batchB + (long)(blockIdx.x * 128);

    const int arow  = tid >> 1;          // 0..127
    const int acol4 = (tid & 1) * 4;     // 0 or 4
    const int brow  = tid >> 5;          // 0..7
    const int bcol4 = (tid & 31) * 4;    // 0..124

    float acc[8][8];
    #pragma unroll
    for (int i = 0; i < 8; i++)
        #pragma unroll
        for (int j = 0; j < 8; j++) acc[i][j] = 0.f;

    for (int k0 = 0; k0 < K; k0 += 8) {
        float4 a4 = *(const float4*)(Ab + (long)arow * lda + k0 + acol4);
        As[acol4 + 0][arow] = a4.x;
        As[acol4 + 1][arow] = a4.y;
        As[acol4 + 2][arow] = a4.z;
        As[acol4 + 3][arow] = a4.w;
        float4 b4 = *(const float4*)(Bb + (long)(k0 + brow) * ldb + bcol4);
        *(float4*)&Bs[brow][bcol4] = b4;
        __syncthreads();

        #pragma unroll
        for (int k = 0; k < 8; k++) {
            float4 a0 = *(const float4*)&As[k][ty * 8];
            float4 a1 = *(const float4*)&As[k][ty * 8 + 4];
            float4 b0 = *(const float4*)&Bs[k][tx * 8];
            float4 b1 = *(const float4*)&Bs[k][tx * 8 + 4];
            float ra[8] = {a0.x, a0.y, a0.z, a0.w, a1.x, a1.y, a1.z, a1.w};
            float rb[8] = {b0.x, b0.y, b0.z, b0.w, b1.x, b1.y, b1.z, b1.w};
            #pragma unroll
            for (int i = 0; i < 8; i++)
                #pragma unroll
                for (int j = 0; j < 8; j++)
                    acc[i][j] += ra[i] * rb[j];
        }
        __syncthreads();
    }

    if constexpr (MODE == 0 || MODE == 1) {
        float* Cb = Cm + (long)blockIdx.z * batchC;
        const int row0 = blockIdx.y * 128 + ty * 8;
        const int col0 = blockIdx.x * 128 + tx * 8;
        #pragma unroll
        for (int i = 0; i < 8; i++) {
            long rbase = (long)(row0 + i) * ldc + col0;
            #pragma unroll
            for (int j = 0; j < 8; j++) {
                float v = acc[i][j];
                if (MODE == 0) { if (bias) v += bias[col0 + j]; }
                else           { v += Cb[rbase + j]; }
                Cb[rbase + j] = v;
            }
        }
    }
    if constexpr (MODE == 2) {
        float s = 0.f;
        #pragma unroll
        for (int i = 0; i < 8; i++)
            #pragma unroll
            for (int j = 0; j < 8; j++) s += acc[i][j] * acc[i][j];
        __shared__ float rb[256];
        rb[tid] = s;
        __syncthreads();
        for (int o = 128; o > 0; o >>= 1) {
            if (tid < o) rb[tid] += rb[tid + o];
            __syncthreads();
        }
        if (tid == 0) {
            int bid = blockIdx.z * gridDim.y * gridDim.x + blockIdx.y * gridDim.x + blockIdx.x;
            red_out[bid] = rb[0];
        }
    }
    if constexpr (MODE == 3) {
        __shared__ float red[128 * 16];
        #pragma unroll
        for (int i = 0; i < 8; i++) {
            float s = 0.f;
            #pragma unroll
            for (int j = 0; j < 8; j++) s += acc[i][j] * acc[i][j];
            red[(ty * 8 + i) * 16 + tx] = s;
        }
        __syncthreads();
        if (tid < 128) {
            float s = 0.f;
            #pragma unroll
            for (int t = 0; t < 16; t++) s += red[tid * 16 + t];
            int row = blockIdx.y * 128 + tid;
            atomicAdd(&red_out[(long)row * red_stride + blockIdx.z], s);
        }
    }
}

// ============================================================================
// Small prep kernels
// ============================================================================
__global__ void k_wmeans(const float* __restrict__ Wb, const float* __restrict__ Wf,
                         const float* __restrict__ bb, const float* __restrict__ bf,
                         float* Wbm, float* Wfm, float* bbm, float* bfm)
{
    int i = blockIdx.x * 256 + threadIdx.x;
    const int s = Cn * CHn;
    if (i < s) {
        Wbm[i] = 0.25f * (Wb[i] + Wb[s + i] + Wb[2 * s + i] + Wb[3 * s + i]);
        Wfm[i] = 0.25f * (Wf[i] + Wf[s + i] + Wf[2 * s + i] + Wf[3 * s + i]);
    }
    if (i < CHn) {
        bbm[i] = 0.25f * (bb[i] + bb[CHn + i] + bb[2 * CHn + i] + bb[3 * CHn + i]);
        bfm[i] = 0.25f * (bf[i] + bf[CHn + i] + bf[2 * CHn + i] + bf[3 * CHn + i]);
    }
}

// A1 = Wbm @ Wt[0:256,:], A2 = Wfm @ Wt[256:512,:]
__global__ void k_precA(const float* __restrict__ Wbm, const float* __restrict__ Wfm,
                        const float* __restrict__ Wt, float* A1, float* A2)
{
    int z = blockIdx.y;
    const float* Wm  = z ? Wfm : Wbm;
    const float* Wts = Wt + z * CHn * Cn;
    float* A = z ? A2 : A1;
    int c = blockIdx.x;
    __shared__ float w[CHn];
    w[threadIdx.x] = Wm[c * CHn + threadIdx.x];
    __syncthreads();
    for (int jj = threadIdx.x; jj < Cn; jj += 256) {
        float acc = 0.f;
        #pragma unroll 8
        for (int d = 0; d < CHn; d++) acc += w[d] * Wts[d * Cn + jj];
        A[c * Cn + jj] = acc;
    }
}

__global__ void k_btot(const float* __restrict__ bbm, const float* __restrict__ bfm,
                       const float* __restrict__ Wt, const float* __restrict__ bt,
                       float* btot)
{
    int j = threadIdx.x;  // 512 threads
    float acc = bt[j];
    for (int d = 0; d < CHn; d++)
        acc += bbm[d] * Wt[d * Cn + j] + bfm[d] * Wt[(CHn + d) * Cn + j];
    btot[j] = acc;
}

// From h: diffused (-> d_out), base, weighted, edge-diffs
__global__ void k_fuse(const float* __restrict__ h, const float* __restrict__ inc,
                       const float* __restrict__ dampp,
                       float* __restrict__ diff, float* __restrict__ base,
                       float* __restrict__ gw, float* __restrict__ gd)
{
    __shared__ float sinc[En * Pn];
    if (threadIdx.x < En * Pn) sinc[threadIdx.x] = inc[threadIdx.x];
    __syncthreads();

    int idx = blockIdx.x * 256 + threadIdx.x;
    if (idx >= Bsz * Cn) return;
    int b = idx / Cn;
    int c = idx % Cn;
    float damping = *dampp;

    float s[4];
    #pragma unroll
    for (int q = 0; q < 4; q++) s[q] = h[(long)b * Hdim + q * Cn + c];

    // L = inc^T inc
    float L[4][4];
    #pragma unroll
    for (int p = 0; p < 4; p++)
        #pragma unroll
        for (int q = 0; q < 4; q++) {
            float a = 0.f;
            #pragma unroll
            for (int e = 0; e < En; e++) a += sinc[e * 4 + p] * sinc[e * 4 + q];
            L[p][q] = a;
        }

    float d[4];
    #pragma unroll
    for (int p = 0; p < 4; p++) {
        float a = 0.f;
        #pragma unroll
        for (int q = 0; q < 4; q++) a += L[p][q] * s[q];
        d[p] = s[p] - damping * a;
        diff[(long)b * Hdim + p * Cn + c] = d[p];
    }
    base[idx] = 0.25f * (d[0] + d[1] + d[2] + d[3]);

    #pragma unroll
    for (int e = 0; e < En; e++) {
        float a = 0.f;
        #pragma unroll
        for (int p = 0; p < 4; p++) a += sinc[e * 4 + p] * s[p];
        gw[((long)b * En + e) * Cn + c] = a;
    }
    const int II[6] = {0, 0, 0, 1, 1, 2};
    const int JJ[6] = {1, 2, 3, 2, 3, 3};
    #pragma unroll
    for (int e = 0; e < En; e++)
        gd[((long)b * En + e) * Cn + c] = d[II[e]] - d[JJ[e]];
}

__global__ void k_h1norm(const float* __restrict__ cobsq, float* __restrict__ out)
{
    int b = blockIdx.x * 256 + threadIdx.x;
    if (b >= Bsz) return;
    float a = 0.f;
    #pragma unroll
    for (int e = 0; e < En; e++) a += sqrtf(cobsq[b * En + e]);
    out[b] = a * (1.0f / En);
}

__global__ void k_h1loss(const float* __restrict__ part, int n, float scale, float* out)
{
    __shared__ float rb[256];
    float s = 0.f;
    for (int i = threadIdx.x; i < n; i += 256) s += part[i];
    rb[threadIdx.x] = s;
    __syncthreads();
    for (int o = 128; o > 0; o >>= 1) {
        if (threadIdx.x < o) rb[threadIdx.x] += rb[threadIdx.x + o];
        __syncthreads();
    }
    if (threadIdx.x == 0) out[0] = rb[0] * scale;
}

__global__ void k_copy(const float* __restrict__ src, float* __restrict__ dst, int n)
{
    int i = blockIdx.x * 256 + threadIdx.x;
    if (i < n) dst[i] = src[i];
}

// ============================================================================
extern "C" void kernel_launch(void* const* d_in, const int* in_sizes, int n_in,
                              void* d_out, int out_size)
{
    const float* x       = (const float*)d_in[0];
    const float* fiber   = (const float*)d_in[1];
    const float* W_in    = (const float*)d_in[2];
    const float* b_in    = (const float*)d_in[3];
    const float* inc     = (const float*)d_in[4];
    const float* sheaf   = (const float*)d_in[5];
    const float* damping = (const float*)d_in[6];
    const float* Wb      = (const float*)d_in[7];
    const float* bb      = (const float*)d_in[8];
    const float* Wf      = (const float*)d_in[9];
    const float* bf      = (const float*)d_in[10];
    const float* Wt      = (const float*)d_in[11];
    const float* bt      = (const float*)d_in[12];
    const float* Wr      = (const float*)d_in[13];
    const float* br      = (const float*)d_in[14];  (void)br;
    const float* Wg      = (const float*)d_in[15];
    const float* bg      = (const float*)d_in[16];
    const float* Wc      = (const float*)d_in[17];
    const float* bc      = (const float*)d_in[18];

    float* out = (float*)d_out;
    void* sp = nullptr;
    cudaGetSymbolAddress(&sp, g_scratch);
    float* S = (float*)sp;

    float* h     = S + OFF_H;
    float* gw    = S + OFF_W;
    float* gd    = S + OFF_D;
    float* glued = S + OFF_GLUED;
    float* base  = S + OFF_BASE;
    float* total = S + OFF_TOTAL;
    float* A1    = S + OFF_A1;
    float* A2    = S + OFF_A2;
    float* Wbm   = S + OFF_WBM;
    float* Wfm   = S + OFF_WFM;
    float* bbm   = S + OFF_BBM;
    float* bfm   = S + OFF_BFM;
    float* btot  = S + OFF_BTOT;
    float* cobsq = S + OFF_COBSQ;
    float* part  = S + OFF_PART;

    float* o_output = out + OUT_OUTPUT;
    float* o_diff   = out + OUT_DIFF;
    float* o_h1n    = out + OUT_H1N;
    float* o_h1l    = out + OUT_H1L;
    float* o_total  = out + OUT_TOTAL;

    // --- precompute collapsed simplex operator ---
    k_wmeans<<<(Cn * CHn + 255) / 256, 256>>>(Wb, Wf, bb, bf, Wbm, Wfm, bbm, bfm);
    k_precA<<<dim3(Cn, 2), 256>>>(Wbm, Wfm, Wt, A1, A2);
    k_btot<<<1, 512>>>(bbm, bfm, Wt, bt, btot);

    // --- h = x @ W_in + b_in ---
    sgemm<0><<<dim3(Hdim / 128, Bsz / 128), 256>>>(
        x, W_in, h, DIN, DIN, Hdim, Hdim, 0, 0, 0, b_in, nullptr, 0);

    // --- diffused / base / weighted / edge-diffs ---
    k_fuse<<<(Bsz * Cn + 255) / 256, 256>>>(h, inc, damping, o_diff, base, gw, gd);

    // --- coboundary row norms: ||weighted[:,e,:] @ sheaf[e]||^2 per (b,e) ---
    cudaMemsetAsync(cobsq, 0, (size_t)Bsz * En * sizeof(float));
    sgemm<3><<<dim3(Cn / 128, Bsz / 128, En), 256>>>(
        gw, sheaf, nullptr, Cn, En * Cn, Cn, 0,
        (long)Cn, (long)Cn * Cn, 0, nullptr, cobsq, En);
    k_h1norm<<<Bsz / 256, 256>>>(cobsq, o_h1n);

    // --- h1_loss: sumsq of (si-sj)@Wr[e] ---
    sgemm<2><<<dim3(CHn / 128, Bsz / 128, En), 256>>>(
        gd, Wr, nullptr, Cn, En * Cn, CHn, 0,
        (long)Cn, (long)Cn * CHn, 0, nullptr, part, 0);
    k_h1loss<<<1, 256>>>(part, (CHn / 128) * (Bsz / 128) * En,
                         1.0f / ((float)Bsz * En * CHn), o_h1l);

    // --- total = base@A1 + fiber@A2 + btot ---
    sgemm<0><<<dim3(Cn / 128, Bsz / 128), 256>>>(
        base, A1, total, Cn, Cn, Cn, Cn, 0, 0, 0, btot, nullptr, 0);
    sgemm<1><<<dim3(Cn / 128, Bsz / 128), 256>>>(
        fiber, A2, total, Cn, Cn, Cn, Cn, 0, 0, 0, nullptr, nullptr, 0);
    k_copy<<<(Bsz * Cn + 255) / 256, 256>>>(total, o_total, Bsz * Cn);

    // --- glued = diffused @ Wg + bg ---
    sgemm<0><<<dim3(Hdim / 128, Bsz / 128), 256>>>(
        o_diff, Wg, glued, Hdim, Hdim, Hdim, Hdim, 0, 0, 0, bg, nullptr, 0);

    // --- output = glued @ Wc[:2048] + total @ Wc[2048:] + bc ---
    sgemm<0><<<dim3(DOUTn / 128, Bsz / 128), 256>>>(
        glued, Wc, o_output, Hdim, Hdim, DOUTn, DOUTn, 0, 0, 0, bc, nullptr, 0);
    sgemm<1><<<dim3(DOUTn / 128, Bsz / 128), 256>>>(
        total, Wc + (long)Hdim * DOUTn, o_output, Cn, Cn, DOUTn, DOUTn, 0, 0, 0,
        nullptr, nullptr, 0);
}

// round 3
// speedup vs baseline: 2.6376x; 2.6376x over previous
#include <cuda_runtime.h>
#include <cuda_bf16.h>
#include <cstdint>
#include <math.h>

#define Bsz  8192
#define DIN  1024
#define Hdim 2048
#define DOUTn 1024
#define Pn   4
#define En   6
#define Cn   512
#define CHn  256

// ---- scratch layout inside one big device array ----
#define OFF_H      0L
#define OFF_W      16777216L
#define OFF_D      41943040L
#define OFF_GLUED  67108864L
#define OFF_BASE   83886080L
#define OFF_TOTAL  88080384L
#define OFF_A1     92274688L
#define OFF_A2     92536832L
#define OFF_WBM    92798976L
#define OFF_WFM    92930048L
#define OFF_BBM    93061120L
#define OFF_BFM    93061376L
#define OFF_BTOT   93061632L
#define OFF_COBSQ  93062144L
#define OFF_PART   93111296L
#define SCRATCH_SZ 93112320L

__device__ float g_scratch[SCRATCH_SZ];

// ---- output layout in d_out (tuple order: output, diffused, h1_norm, h1_loss, total) ----
#define OUT_OUTPUT 0L
#define OUT_DIFF   8388608L
#define OUT_H1N    25165824L
#define OUT_H1L    25174016L
#define OUT_TOTAL  25174017L

// ============================================================================
// Tensor-core fp32 GEMM via bf16 hi/lo split (3 MMA passes: hh + hl + lh).
// Block tile 128x128, BK=16, 256 threads (8 warps, 2x4), warp tile 64x32.
// MODE 0: C = acc (+ bias[col])
// MODE 1: C += acc
// MODE 2: red_out[blockLinear] = sum(acc^2)
// MODE 3: atomicAdd(red_out[row*red_stride + z], rowsumsq)
// Requires M%128==0, N%128==0, K%16==0.
// ============================================================================

#define LDSM4(r, p) { unsigned int _a = (unsigned int)__cvta_generic_to_shared(p); \
  asm volatile("ldmatrix.sync.aligned.m8n8.x4.shared.b16 {%0,%1,%2,%3}, [%4];"     \
  : "=r"((r)[0]), "=r"((r)[1]), "=r"((r)[2]), "=r"((r)[3]) : "r"(_a)); }

#define LDSM4T(r0,r1,r2,r3, p) { unsigned int _a = (unsigned int)__cvta_generic_to_shared(p); \
  asm volatile("ldmatrix.sync.aligned.m8n8.x4.trans.shared.b16 {%0,%1,%2,%3}, [%4];"          \
  : "=r"(r0), "=r"(r1), "=r"(r2), "=r"(r3) : "r"(_a)); }

#define MMA16816(d, a, b) asm volatile(                                         \
  "mma.sync.aligned.m16n8k16.row.col.f32.bf16.bf16.f32 "                        \
  "{%0,%1,%2,%3}, {%4,%5,%6,%7}, {%8,%9}, {%0,%1,%2,%3};"                       \
  : "+f"((d)[0]), "+f"((d)[1]), "+f"((d)[2]), "+f"((d)[3])                      \
  : "r"((a)[0]), "r"((a)[1]), "r"((a)[2]), "r"((a)[3]),                         \
    "r"((b)[0]), "r"((b)[1]))

__device__ __forceinline__ unsigned int bpack(__nv_bfloat16 a, __nv_bfloat16 b) {
    __nv_bfloat162 t = __halves2bfloat162(a, b);
    return *reinterpret_cast<unsigned int*>(&t);
}

// convert 8 fp32 -> 8 bf16 hi + 8 bf16 lo, one 16B store each
__device__ __forceinline__ void cvt8(const float4& v0, const float4& v1,
                                     __nv_bfloat16* dh, __nv_bfloat16* dl)
{
    float f[8] = {v0.x, v0.y, v0.z, v0.w, v1.x, v1.y, v1.z, v1.w};
    __nv_bfloat16 h[8], l[8];
    #pragma unroll
    for (int i = 0; i < 8; i++) {
        h[i] = __float2bfloat16(f[i]);
        l[i] = __float2bfloat16(f[i] - __bfloat162float(h[i]));
    }
    uint4 uh, ul;
    uh.x = bpack(h[0], h[1]); uh.y = bpack(h[2], h[3]);
    uh.z = bpack(h[4], h[5]); uh.w = bpack(h[6], h[7]);
    ul.x = bpack(l[0], l[1]); ul.y = bpack(l[2], l[3]);
    ul.z = bpack(l[4], l[5]); ul.w = bpack(l[6], l[7]);
    *reinterpret_cast<uint4*>(dh) = uh;
    *reinterpret_cast<uint4*>(dl) = ul;
}

template<int MODE>
__global__ __launch_bounds__(256)
void tgemm(const float* __restrict__ A, const float* __restrict__ Bm,
           float* __restrict__ Cm,
           int K, int lda, int ldb, int ldc,
           long batchA, long batchB, long batchC,
           const float* __restrict__ bias,
           float* __restrict__ red_out, int red_stride)
{
    __shared__ __align__(16) __nv_bfloat16 Ahs[2][128][24];
    __shared__ __align__(16) __nv_bfloat16 Als[2][128][24];
    __shared__ __align__(16) __nv_bfloat16 Bhs[2][16][136];
    __shared__ __align__(16) __nv_bfloat16 Bls[2][16][136];

    const int tid  = threadIdx.x;
    const int lane = tid & 31;
    const int warp = tid >> 5;
    const int wm = warp >> 2;       // 0..1
    const int wn = warp & 3;        // 0..3

    const float* Ab = A  + (long)blockIdx.z * batchA + (long)(blockIdx.y * 128) * lda;
    const float* Bb = Bm + (long)blockIdx.z * batchB + (long)(blockIdx.x * 128);

    const int arow = tid >> 1,  ac0 = (tid & 1) * 8;    // A: 128 rows x 16 cols
    const int brow = tid >> 4,  bc0 = (tid & 15) * 8;   // B: 16 rows x 128 cols

    float acc[4][4][4];
    #pragma unroll
    for (int i = 0; i < 4; i++)
        #pragma unroll
        for (int j = 0; j < 4; j++)
            #pragma unroll
            for (int k = 0; k < 4; k++) acc[i][j][k] = 0.f;

    // prologue: stage 0
    {
        const float* ap = Ab + (long)arow * lda + ac0;
        float4 a0 = *(const float4*)(ap);
        float4 a1 = *(const float4*)(ap + 4);
        const float* bp = Bb + (long)brow * ldb + bc0;
        float4 b0 = *(const float4*)(bp);
        float4 b1 = *(const float4*)(bp + 4);
        cvt8(a0, a1, &Ahs[0][arow][ac0], &Als[0][arow][ac0]);
        cvt8(b0, b1, &Bhs[0][brow][bc0], &Bls[0][brow][bc0]);
    }

    const int nst = K >> 4;
    int cur = 0;
    const int lr = lane & 15;
    const int lc = (lane >> 4) << 3;

    for (int s = 0; s < nst; s++) {
        __syncthreads();
        const bool pf = (s + 1 < nst);
        float4 pa0, pa1, pb0, pb1;
        if (pf) {
            const int k0 = (s + 1) << 4;
            const float* ap = Ab + (long)arow * lda + k0 + ac0;
            pa0 = *(const float4*)(ap);
            pa1 = *(const float4*)(ap + 4);
            const float* bp = Bb + (long)(k0 + brow) * ldb + bc0;
            pb0 = *(const float4*)(bp);
            pb1 = *(const float4*)(bp + 4);
        }

        // ---- load fragments ----
        unsigned int ah[4][4], al4[4][4], bh[4][2], bl4[4][2];
        #pragma unroll
        for (int mt = 0; mt < 4; mt++) {
            LDSM4(ah[mt],  &Ahs[cur][wm * 64 + mt * 16 + lr][lc]);
            LDSM4(al4[mt], &Als[cur][wm * 64 + mt * 16 + lr][lc]);
        }
        #pragma unroll
        for (int np = 0; np < 2; np++) {
            unsigned int r0, r1, r2, r3;
            LDSM4T(r0, r1, r2, r3, &Bhs[cur][lr][wn * 32 + np * 16 + lc]);
            bh[np * 2][0] = r0; bh[np * 2][1] = r1;
            bh[np * 2 + 1][0] = r2; bh[np * 2 + 1][1] = r3;
            LDSM4T(r0, r1, r2, r3, &Bls[cur][lr][wn * 32 + np * 16 + lc]);
            bl4[np * 2][0] = r0; bl4[np * 2][1] = r1;
            bl4[np * 2 + 1][0] = r2; bl4[np * 2 + 1][1] = r3;
        }

        // ---- 3 passes: hh, hl, lh ----
        #pragma unroll
        for (int mt = 0; mt < 4; mt++)
            #pragma unroll
            for (int nt = 0; nt < 4; nt++)
                MMA16816(acc[mt][nt], ah[mt], bh[nt]);
        #pragma unroll
        for (int mt = 0; mt < 4; mt++)
            #pragma unroll
            for (int nt = 0; nt < 4; nt++)
                MMA16816(acc[mt][nt], ah[mt], bl4[nt]);
        #pragma unroll
        for (int mt = 0; mt < 4; mt++)
            #pragma unroll
            for (int nt = 0; nt < 4; nt++)
                MMA16816(acc[mt][nt], al4[mt], bh[nt]);

        if (pf) {
            cvt8(pa0, pa1, &Ahs[cur ^ 1][arow][ac0], &Als[cur ^ 1][arow][ac0]);
            cvt8(pb0, pb1, &Bhs[cur ^ 1][brow][bc0], &Bls[cur ^ 1][brow][bc0]);
        }
        cur ^= 1;
    }

    // ---- epilogues ----
    if constexpr (MODE == 0 || MODE == 1) {
        float* Cb = Cm + (long)blockIdx.z * batchC;
        const int rb = blockIdx.y * 128 + wm * 64;
        const int cb = blockIdx.x * 128 + wn * 32;
        #pragma unroll
        for (int mt = 0; mt < 4; mt++) {
            const int r = rb + mt * 16 + (lane >> 2);
            #pragma unroll
            for (int nt = 0; nt < 4; nt++) {
                const int c = cb + nt * 8 + (lane & 3) * 2;
                float2 v0 = make_float2(acc[mt][nt][0], acc[mt][nt][1]);
                float2 v1 = make_float2(acc[mt][nt][2], acc[mt][nt][3]);
                if constexpr (MODE == 0) {
                    if (bias) {
                        float b0 = bias[c], b1 = bias[c + 1];
                        v0.x += b0; v0.y += b1; v1.x += b0; v1.y += b1;
                    }
                } else {
                    float2 o0 = *(float2*)&Cb[(long)r * ldc + c];
                    float2 o1 = *(float2*)&Cb[(long)(r + 8) * ldc + c];
                    v0.x += o0.x; v0.y += o0.y; v1.x += o1.x; v1.y += o1.y;
                }
                *(float2*)&Cb[(long)r * ldc + c] = v0;
                *(float2*)&Cb[(long)(r + 8) * ldc + c] = v1;
            }
        }
    }
    if constexpr (MODE == 2) {
        float s = 0.f;
        #pragma unroll
        for (int mt = 0; mt < 4; mt++)
            #pragma unroll
            for (int nt = 0; nt < 4; nt++)
                #pragma unroll
                for (int k = 0; k < 4; k++) s += acc[mt][nt][k] * acc[mt][nt][k];
        __shared__ float redsh[256];
        redsh[tid] = s;
        __syncthreads();
        for (int o = 128; o > 0; o >>= 1) {
            if (tid < o) redsh[tid] += redsh[tid + o];
            __syncthreads();
        }
        if (tid == 0) {
            int bid = blockIdx.z * gridDim.y * gridDim.x + blockIdx.y * gridDim.x + blockIdx.x;
            red_out[bid] = redsh[0];
        }
    }
    if constexpr (MODE == 3) {
        const int rb = blockIdx.y * 128 + wm * 64;
        #pragma unroll
        for (int mt = 0; mt < 4; mt++) {
            float s0 = 0.f, s1 = 0.f;
            #pragma unroll
            for (int nt = 0; nt < 4; nt++) {
                s0 += acc[mt][nt][0] * acc[mt][nt][0] + acc[mt][nt][1] * acc[mt][nt][1];
                s1 += acc[mt][nt][2] * acc[mt][nt][2] + acc[mt][nt][3] * acc[mt][nt][3];
            }
            s0 += __shfl_xor_sync(0xffffffff, s0, 1);
            s0 += __shfl_xor_sync(0xffffffff, s0, 2);
            s1 += __shfl_xor_sync(0xffffffff, s1, 1);
            s1 += __shfl_xor_sync(0xffffffff, s1, 2);
            if ((lane & 3) == 0) {
                const int r = rb + mt * 16 + (lane >> 2);
                atomicAdd(&red_out[(long)r * red_stride + blockIdx.z], s0);
                atomicAdd(&red_out[(long)(r + 8) * red_stride + blockIdx.z], s1);
            }
        }
    }
}

// ============================================================================
// Small prep kernels
// ============================================================================
__global__ void k_wmeans(const float* __restrict__ Wb, const float* __restrict__ Wf,
                         const float* __restrict__ bb, const float* __restrict__ bf,
                         float* Wbm, float* Wfm, float* bbm, float* bfm)
{
    int i = blockIdx.x * 256 + threadIdx.x;
    const int s = Cn * CHn;
    if (i < s) {
        Wbm[i] = 0.25f * (Wb[i] + Wb[s + i] + Wb[2 * s + i] + Wb[3 * s + i]);
        Wfm[i] = 0.25f * (Wf[i] + Wf[s + i] + Wf[2 * s + i] + Wf[3 * s + i]);
    }
    if (i < CHn) {
        bbm[i] = 0.25f * (bb[i] + bb[CHn + i] + bb[2 * CHn + i] + bb[3 * CHn + i]);
        bfm[i] = 0.25f * (bf[i] + bf[CHn + i] + bf[2 * CHn + i] + bf[3 * CHn + i]);
    }
}

// A1 = Wbm @ Wt[0:256,:], A2 = Wfm @ Wt[256:512,:]
__global__ void k_precA(const float* __restrict__ Wbm, const float* __restrict__ Wfm,
                        const float* __restrict__ Wt, float* A1, float* A2)
{
    int z = blockIdx.y;
    const float* Wm  = z ? Wfm : Wbm;
    const float* Wts = Wt + z * CHn * Cn;
    float* A = z ? A2 : A1;
    int c = blockIdx.x;
    __shared__ float w[CHn];
    w[threadIdx.x] = Wm[c * CHn + threadIdx.x];
    __syncthreads();
    for (int jj = threadIdx.x; jj < Cn; jj += 256) {
        float acc = 0.f;
        #pragma unroll 8
        for (int d = 0; d < CHn; d++) acc += w[d] * Wts[d * Cn + jj];
        A[c * Cn + jj] = acc;
    }
}

__global__ void k_btot(const float* __restrict__ bbm, const float* __restrict__ bfm,
                       const float* __restrict__ Wt, const float* __restrict__ bt,
                       float* btot)
{
    int j = threadIdx.x;  // 512 threads
    float acc = bt[j];
    for (int d = 0; d < CHn; d++)
        acc += bbm[d] * Wt[d * Cn + j] + bfm[d] * Wt[(CHn + d) * Cn + j];
    btot[j] = acc;
}

// From h: diffused (-> d_out), base, weighted, edge-diffs
__global__ void k_fuse(const float* __restrict__ h, const float* __restrict__ inc,
                       const float* __restrict__ dampp,
                       float* __restrict__ diff, float* __restrict__ base,
                       float* __restrict__ gw, float* __restrict__ gd)
{
    __shared__ float sinc[En * Pn];
    if (threadIdx.x < En * Pn) sinc[threadIdx.x] = inc[threadIdx.x];
    __syncthreads();

    int idx = blockIdx.x * 256 + threadIdx.x;
    if (idx >= Bsz * Cn) return;
    int b = idx / Cn;
    int c = idx % Cn;
    float damping = *dampp;

    float s[4];
    #pragma unroll
    for (int q = 0; q < 4; q++) s[q] = h[(long)b * Hdim + q * Cn + c];

    float L[4][4];
    #pragma unroll
    for (int p = 0; p < 4; p++)
        #pragma unroll
        for (int q = 0; q < 4; q++) {
            float a = 0.f;
            #pragma unroll
            for (int e = 0; e < En; e++) a += sinc[e * 4 + p] * sinc[e * 4 + q];
            L[p][q] = a;
        }

    float d[4];
    #pragma unroll
    for (int p = 0; p < 4; p++) {
        float a = 0.f;
        #pragma unroll
        for (int q = 0; q < 4; q++) a += L[p][q] * s[q];
        d[p] = s[p] - damping * a;
        diff[(long)b * Hdim + p * Cn + c] = d[p];
    }
    base[idx] = 0.25f * (d[0] + d[1] + d[2] + d[3]);

    #pragma unroll
    for (int e = 0; e < En; e++) {
        float a = 0.f;
        #pragma unroll
        for (int p = 0; p < 4; p++) a += sinc[e * 4 + p] * s[p];
        gw[((long)b * En + e) * Cn + c] = a;
    }
    const int II[6] = {0, 0, 0, 1, 1, 2};
    const int JJ[6] = {1, 2, 3, 2, 3, 3};
    #pragma unroll
    for (int e = 0; e < En; e++)
        gd[((long)b * En + e) * Cn + c] = d[II[e]] - d[JJ[e]];
}

__global__ void k_h1norm(const float* __restrict__ cobsq, float* __restrict__ out)
{
    int b = blockIdx.x * 256 + threadIdx.x;
    if (b >= Bsz) return;
    float a = 0.f;
    #pragma unroll
    for (int e = 0; e < En; e++) a += sqrtf(cobsq[b * En + e]);
    out[b] = a * (1.0f / En);
}

__global__ void k_h1loss(const float* __restrict__ part, int n, float scale, float* out)
{
    __shared__ float rb[256];
    float s = 0.f;
    for (int i = threadIdx.x; i < n; i += 256) s += part[i];
    rb[threadIdx.x] = s;
    __syncthreads();
    for (int o = 128; o > 0; o >>= 1) {
        if (threadIdx.x < o) rb[threadIdx.x] += rb[threadIdx.x + o];
        __syncthreads();
    }
    if (threadIdx.x == 0) out[0] = rb[0] * scale;
}

__global__ void k_copy(const float* __restrict__ src, float* __restrict__ dst, int n)
{
    int i = blockIdx.x * 256 + threadIdx.x;
    if (i < n) dst[i] = src[i];
}

// ============================================================================
extern "C" void kernel_launch(void* const* d_in, const int* in_sizes, int n_in,
                              void* d_out, int out_size)
{
    const float* x       = (const float*)d_in[0];
    const float* fiber   = (const float*)d_in[1];
    const float* W_in    = (const float*)d_in[2];
    const float* b_in    = (const float*)d_in[3];
    const float* inc     = (const float*)d_in[4];
    const float* sheaf   = (const float*)d_in[5];
    const float* damping = (const float*)d_in[6];
    const float* Wb      = (const float*)d_in[7];
    const float* bb      = (const float*)d_in[8];
    const float* Wf      = (const float*)d_in[9];
    const float* bf      = (const float*)d_in[10];
    const float* Wt      = (const float*)d_in[11];
    const float* bt      = (const float*)d_in[12];
    const float* Wr      = (const float*)d_in[13];
    const float* br      = (const float*)d_in[14];  (void)br;
    const float* Wg      = (const float*)d_in[15];
    const float* bg      = (const float*)d_in[16];
    const float* Wc      = (const float*)d_in[17];
    const float* bc      = (const float*)d_in[18];

    float* out = (float*)d_out;
    void* sp = nullptr;
    cudaGetSymbolAddress(&sp, g_scratch);
    float* S = (float*)sp;

    float* h     = S + OFF_H;
    float* gw    = S + OFF_W;
    float* gd    = S + OFF_D;
    float* glued = S + OFF_GLUED;
    float* base  = S + OFF_BASE;
    float* total = S + OFF_TOTAL;
    float* A1    = S + OFF_A1;
    float* A2    = S + OFF_A2;
    float* Wbm   = S + OFF_WBM;
    float* Wfm   = S + OFF_WFM;
    float* bbm   = S + OFF_BBM;
    float* bfm   = S + OFF_BFM;
    float* btot  = S + OFF_BTOT;
    float* cobsq = S + OFF_COBSQ;
    float* part  = S + OFF_PART;

    float* o_output = out + OUT_OUTPUT;
    float* o_diff   = out + OUT_DIFF;
    float* o_h1n    = out + OUT_H1N;
    float* o_h1l    = out + OUT_H1L;
    float* o_total  = out + OUT_TOTAL;

    // --- precompute collapsed simplex operator ---
    k_wmeans<<<(Cn * CHn + 255) / 256, 256>>>(Wb, Wf, bb, bf, Wbm, Wfm, bbm, bfm);
    k_precA<<<dim3(Cn, 2), 256>>>(Wbm, Wfm, Wt, A1, A2);
    k_btot<<<1, 512>>>(bbm, bfm, Wt, bt, btot);

    // --- h = x @ W_in + b_in ---
    tgemm<0><<<dim3(Hdim / 128, Bsz / 128), 256>>>(
        x, W_in, h, DIN, DIN, Hdim, Hdim, 0, 0, 0, b_in, nullptr, 0);

    // --- diffused / base / weighted / edge-diffs ---
    k_fuse<<<(Bsz * Cn + 255) / 256, 256>>>(h, inc, damping, o_diff, base, gw, gd);

    // --- coboundary row norms: ||weighted[:,e,:] @ sheaf[e]||^2 per (b,e) ---
    cudaMemsetAsync(cobsq, 0, (size_t)Bsz * En * sizeof(float));
    tgemm<3><<<dim3(Cn / 128, Bsz / 128, En), 256>>>(
        gw, sheaf, nullptr, Cn, En * Cn, Cn, 0,
        (long)Cn, (long)Cn * Cn, 0, nullptr, cobsq, En);
    k_h1norm<<<Bsz / 256, 256>>>(cobsq, o_h1n);

    // --- h1_loss: sumsq of (si-sj)@Wr[e] ---
    tgemm<2><<<dim3(CHn / 128, Bsz / 128, En), 256>>>(
        gd, Wr, nullptr, Cn, En * Cn, CHn, 0,
        (long)Cn, (long)Cn * CHn, 0, nullptr, part, 0);
    k_h1loss<<<1, 256>>>(part, (CHn / 128) * (Bsz / 128) * En,
                         1.0f / ((float)Bsz * En * CHn), o_h1l);

    // --- total = base@A1 + fiber@A2 + btot ---
    tgemm<0><<<dim3(Cn / 128, Bsz / 128), 256>>>(
        base, A1, total, Cn, Cn, Cn, Cn, 0, 0, 0, btot, nullptr, 0);
    tgemm<1><<<dim3(Cn / 128, Bsz / 128), 256>>>(
        fiber, A2, total, Cn, Cn, Cn, Cn, 0, 0, 0, nullptr, nullptr, 0);
    k_copy<<<(Bsz * Cn + 255) / 256, 256>>>(total, o_total, Bsz * Cn);

    // --- glued = diffused @ Wg + bg ---
    tgemm<0><<<dim3(Hdim / 128, Bsz / 128), 256>>>(
        o_diff, Wg, glued, Hdim, Hdim, Hdim, Hdim, 0, 0, 0, bg, nullptr, 0);

    // --- output = glued @ Wc[:2048] + total @ Wc[2048:] + bc ---
    tgemm<0><<<dim3(DOUTn / 128, Bsz / 128), 256>>>(
        glued, Wc, o_output, Hdim, Hdim, DOUTn, DOUTn, 0, 0, 0, bc, nullptr, 0);
    tgemm<1><<<dim3(DOUTn / 128, Bsz / 128), 256>>>(
        total, Wc + (long)Hdim * DOUTn, o_output, Cn, Cn, DOUTn, DOUTn, 0, 0, 0,
        nullptr, nullptr, 0);
}